// round 2
// baseline (speedup 1.0000x reference)
#include <cuda_runtime.h>

#define B_ 8
#define N_ 2048
#define F_ 64
#define O_ 64
#define BM 128
#define BK 16
#define ALPHA 0.2f

// Scratch (allocation-free rule: __device__ globals)
__device__ float g_d[B_ * N_];              // 64 KB: d[b,n] = rsqrt(rowsum+1)
__device__ float g_Y[(size_t)B_ * N_ * O_]; // 4 MB: Y[b,m,o] = d[b,m] * (X@W)[b,m,o]

// ---------------------------------------------------------------------------
// Pass 1: per A-row rowsum -> d, fused with Y = d * (X @ W).
// One warp per row (8 rows / 256-thread block). A read: 134 MB (HBM-bound).
// ---------------------------------------------------------------------------
__global__ void __launch_bounds__(256) prep_kernel(const float* __restrict__ A,
                                                   const float* __restrict__ X,
                                                   const float* __restrict__ W) {
    __shared__ float sW[F_ * O_];
    __shared__ float sX[8][F_];
    const int t = threadIdx.x;
    const int warp = t >> 5;
    const int lane = t & 31;
    const int row = blockIdx.x * 8 + warp;   // flattened [b][n], 0..16383

    // Stage W (16 KB) and this block's 8 X rows into smem
    #pragma unroll
    for (int i = t; i < F_ * O_; i += 256) sW[i] = W[i];
    #pragma unroll
    for (int i = t; i < 8 * F_; i += 256)
        sX[i >> 6][i & 63] = X[(size_t)blockIdx.x * 8 * F_ + i];
    __syncthreads();

    // Rowsum of A[row, :] with float4 loads
    const float4* arow = (const float4*)(A + (size_t)row * N_);
    float s = 0.f;
    #pragma unroll 4
    for (int i = lane; i < N_ / 4; i += 32) {
        float4 v = arow[i];
        s += (v.x + v.y) + (v.z + v.w);
    }
    #pragma unroll
    for (int off = 16; off; off >>= 1) s += __shfl_xor_sync(0xffffffffu, s, off);
    const float dd = rsqrtf(s + 1.0f);
    if (lane == 0) g_d[row] = dd;

    // Y[row, o] = dd * sum_f X[row,f] * W[f,o]; each lane does o=lane, lane+32
    float acc0 = 0.f, acc1 = 0.f;
    #pragma unroll
    for (int f = 0; f < F_; f++) {
        const float xv = sX[warp][f];
        acc0 += xv * sW[f * O_ + lane];
        acc1 += xv * sW[f * O_ + lane + 32];
    }
    g_Y[(size_t)row * O_ + lane]      = dd * acc0;
    g_Y[(size_t)row * O_ + lane + 32] = dd * acc1;
}

// ---------------------------------------------------------------------------
// Pass 2: Z = A @ Y per batch, fused with:
//   - A copy-out to d_out (written from the tile-load registers; guarded)
//   - epilogue: out = leaky(d[n] * (Z[n,o] + Y[n,o]) + bias[o])
//     (the +Y[n,o] term is the identity's diagonal contribution)
// BM=128 x O=64 tile, BK=16, 256 threads, 8x4 register tile, double-buffered.
// Grid (N/BM=16, B=8) = 128 blocks ~ one wave on 148 SMs.
// ---------------------------------------------------------------------------
__global__ void __launch_bounds__(256, 1) gemm_kernel(const float* __restrict__ A,
                                                      const float* __restrict__ bias,
                                                      float* __restrict__ outX,
                                                      float* __restrict__ outA) {
    __shared__ float As[2][BK][BM];
    __shared__ float Ys[2][BK][O_];

    const int b = blockIdx.y;
    const int rowBase = blockIdx.x * BM;
    const float* Ab = A + (size_t)b * N_ * N_;
    float* outAb = outA ? outA + (size_t)b * N_ * N_ : nullptr;
    const float* Yb = g_Y + (size_t)b * N_ * O_;

    const int t = threadIdx.x;
    const int tx = t & 15;   // output col group: cols tx*4 .. tx*4+3
    const int ty = t >> 4;   // output rows: ty + 16*i, i=0..7

    // A-tile: 128x16 floats = 512 float4; 2 per thread
    const int ar0 = t >> 2;       // 0..63
    const int ac0 = t & 3;        // float4 index within row (k-offset ac0*4)
    const int ar1 = ar0 + 64;

    float4 pa0, pa1, py;
    float acc[8][4];
    #pragma unroll
    for (int i = 0; i < 8; i++)
        #pragma unroll
        for (int j = 0; j < 4; j++) acc[i][j] = 0.f;

    auto load_tile = [&](int k0) {
        const size_t o0 = (size_t)(rowBase + ar0) * N_ + k0 + ac0 * 4;
        const size_t o1 = (size_t)(rowBase + ar1) * N_ + k0 + ac0 * 4;
        pa0 = *(const float4*)(Ab + o0);
        pa1 = *(const float4*)(Ab + o1);
        py  = *(const float4*)(Yb + (size_t)(k0 + ty) * O_ + tx * 4);
        // A copy-through to output (each element loaded exactly once)
        if (outAb) {
            *(float4*)(outAb + o0) = pa0;
            *(float4*)(outAb + o1) = pa1;
        }
    };
    auto store_tile = [&](int buf) {
        As[buf][ac0 * 4 + 0][ar0] = pa0.x;
        As[buf][ac0 * 4 + 1][ar0] = pa0.y;
        As[buf][ac0 * 4 + 2][ar0] = pa0.z;
        As[buf][ac0 * 4 + 3][ar0] = pa0.w;
        As[buf][ac0 * 4 + 0][ar1] = pa1.x;
        As[buf][ac0 * 4 + 1][ar1] = pa1.y;
        As[buf][ac0 * 4 + 2][ar1] = pa1.z;
        As[buf][ac0 * 4 + 3][ar1] = pa1.w;
        *(float4*)&Ys[buf][ty][tx * 4] = py;
    };

    load_tile(0);
    store_tile(0);
    __syncthreads();

    const int NT = N_ / BK;  // 128
    for (int kt = 0; kt < NT; kt++) {
        if (kt + 1 < NT) load_tile((kt + 1) * BK);   // global prefetch in flight
        const int buf = kt & 1;
        #pragma unroll
        for (int k = 0; k < BK; k++) {
            float ra[8];
            #pragma unroll
            for (int i = 0; i < 8; i++) ra[i] = As[buf][k][ty + 16 * i];
            const float4 rb = *(const float4*)&Ys[buf][k][tx * 4];
            #pragma unroll
            for (int i = 0; i < 8; i++) {
                acc[i][0] += ra[i] * rb.x;
                acc[i][1] += ra[i] * rb.y;
                acc[i][2] += ra[i] * rb.z;
                acc[i][3] += ra[i] * rb.w;
            }
        }
        if (kt + 1 < NT) store_tile((kt + 1) & 1);
        __syncthreads();
    }

    // Epilogue: +diagonal term, row scale, bias, leaky relu
    const float4 bv = *(const float4*)(bias + tx * 4);
    #pragma unroll
    for (int i = 0; i < 8; i++) {
        const int n = rowBase + ty + 16 * i;
        const float dn = g_d[(size_t)b * N_ + n];
        const float4 yn = *(const float4*)(Yb + (size_t)n * O_ + tx * 4);
        float4 o;
        o.x = dn * (acc[i][0] + yn.x) + bv.x;
        o.y = dn * (acc[i][1] + yn.y) + bv.y;
        o.z = dn * (acc[i][2] + yn.z) + bv.z;
        o.w = dn * (acc[i][3] + yn.w) + bv.w;
        o.x = fmaxf(o.x, ALPHA * o.x);  // leaky: valid since ALPHA < 1
        o.y = fmaxf(o.y, ALPHA * o.y);
        o.z = fmaxf(o.z, ALPHA * o.z);
        o.w = fmaxf(o.w, ALPHA * o.w);
        *(float4*)(outX + ((size_t)b * N_ + n) * O_ + tx * 4) = o;
    }
}

extern "C" void kernel_launch(void* const* d_in, const int* in_sizes, int n_in,
                              void* d_out, int out_size) {
    const float* X    = (const float*)d_in[0];  // [B, N, F]
    const float* A    = (const float*)d_in[1];  // [B, N, N]
    const float* W    = (const float*)d_in[2];  // [F, O]
    const float* bias = (const float*)d_in[3];  // [O]

    const size_t nX = (size_t)B_ * N_ * O_;     // 1,048,576
    const size_t nA = (size_t)B_ * N_ * N_;     // 33,554,432

    float* outX = (float*)d_out;                // [B, N, O]
    // A pass-through only if the output buffer actually has room for it.
    float* outA = ((size_t)out_size >= nX + nA) ? outX + nX : nullptr;

    prep_kernel<<<B_ * N_ / 8, 256>>>(A, X, W);
    dim3 grid(N_ / BM, B_);
    gemm_kernel<<<grid, 256>>>(A, bias, outX, outA);
}

// round 7
// speedup vs baseline: 1.3280x; 1.3280x over previous
#include <cuda_runtime.h>
#include <cstdint>

#define B_ 8
#define N_ 2048
#define F_ 64
#define O_ 64
#define ALPHA 0.2f

#define BM  128
#define BKC 16
#define NC  (N_ / BKC)        // 128 chunks
#define SA_STRIDE 36          // floats; 36%32==4 -> A-frag lanes g*4+tig distinct
#define SY_STRIDE 72          // floats; 72%32==8 -> B-frag lanes tig*8+g distinct; >= 64 cols
#define SA_BUF (BM * SA_STRIDE)   // 4608 floats
#define SY_BUF (BKC * SY_STRIDE)  // 1152 floats
// total static smem: 2*(4608+1152)*4 = 46080 B < 48 KB

// Scratch (allocation-free rule: __device__ globals)
__device__ float g_d[B_ * N_];               // d[b,n] = rsqrt(rowsum+1)
__device__ float g_Y[(size_t)B_ * N_ * O_];  // Y[b,k,o] = d[b,k]*(X@W)[b,k,o]

// ---------------------------------------------------------------------------
// Pass 1: per A-row rowsum -> d, fused with Y = d*(X@W).
// ---------------------------------------------------------------------------
__global__ void __launch_bounds__(256) prep_kernel(const float* __restrict__ A,
                                                   const float* __restrict__ X,
                                                   const float* __restrict__ W) {
    __shared__ float sW[F_ * O_];
    __shared__ float sX[8][F_];
    const int t = threadIdx.x;
    const int warp = t >> 5;
    const int lane = t & 31;
    const int row = blockIdx.x * 8 + warp;   // flattened [b][n]

    #pragma unroll
    for (int i = t; i < F_ * O_; i += 256) sW[i] = W[i];
    #pragma unroll
    for (int i = t; i < 8 * F_; i += 256)
        sX[i >> 6][i & 63] = X[(size_t)blockIdx.x * 8 * F_ + i];
    __syncthreads();

    const float4* arow = (const float4*)(A + (size_t)row * N_);
    float s = 0.f;
    #pragma unroll 4
    for (int i = lane; i < N_ / 4; i += 32) {
        float4 v = arow[i];
        s += (v.x + v.y) + (v.z + v.w);
    }
    #pragma unroll
    for (int off = 16; off; off >>= 1) s += __shfl_xor_sync(0xffffffffu, s, off);
    const float dd = rsqrtf(s + 1.0f);
    if (lane == 0) g_d[row] = dd;

    float acc0 = 0.f, acc1 = 0.f;
    #pragma unroll
    for (int f = 0; f < F_; f++) {
        const float xv = sX[warp][f];
        acc0 += xv * sW[f * O_ + lane];
        acc1 += xv * sW[f * O_ + lane + 32];
    }
    g_Y[(size_t)row * O_ + lane]      = dd * acc0;
    g_Y[(size_t)row * O_ + lane + 32] = dd * acc1;
}

// ---------------------------------------------------------------------------
// TF32 helpers (sm_80+ PTX; compiles for plain sm_100)
// ---------------------------------------------------------------------------
__device__ __forceinline__ void split_tf32(float x, uint32_t& hi, uint32_t& lo) {
    asm("cvt.rna.tf32.f32 %0, %1;" : "=r"(hi) : "f"(x));
    const float l = x - __uint_as_float(hi);
    asm("cvt.rna.tf32.f32 %0, %1;" : "=r"(lo) : "f"(l));
}
__device__ __forceinline__ void mma8(float* c, const uint32_t* a, const uint32_t* b) {
    asm("mma.sync.aligned.m16n8k8.row.col.f32.tf32.tf32.f32 "
        "{%0,%1,%2,%3}, {%4,%5,%6,%7}, {%8,%9}, {%0,%1,%2,%3};"
        : "+f"(c[0]), "+f"(c[1]), "+f"(c[2]), "+f"(c[3])
        : "r"(a[0]), "r"(a[1]), "r"(a[2]), "r"(a[3]), "r"(b[0]), "r"(b[1]));
}

// ---------------------------------------------------------------------------
// Pass 2: Z = A @ Y via mma.sync tf32 (3xTF32 split), fused A copy-out +
// epilogue out = leaky(d[n]*(Z + Y[n,:]) + bias).
// 128 CTAs (16 row-tiles x 8 batches), 256 threads (8 warps, 4x2 warp grid,
// 32x32 warp tile), double-buffered raw-fp32 SMEM tiles, split in registers.
// ---------------------------------------------------------------------------
__global__ void __launch_bounds__(256, 1) gemm_tc(const float* __restrict__ A,
                                                  const float* __restrict__ bias,
                                                  float* __restrict__ outX,
                                                  float* __restrict__ outA) {
    __shared__ float sA[2 * SA_BUF];
    __shared__ float sY[2 * SY_BUF];

    const int b = blockIdx.y;
    const int rowBase = blockIdx.x * BM;
    const float* Ab = A + (size_t)b * N_ * N_;
    float* outAb = outA ? outA + (size_t)b * N_ * N_ : nullptr;
    const float* Yb = g_Y + (size_t)b * N_ * O_;

    const int t = threadIdx.x;
    const int w = t >> 5;
    const int lane = t & 31;
    const int g = lane >> 2;      // fragment group (0..7)
    const int tig = lane & 3;     // thread-in-group
    const int wm = w & 3;         // warp row-block (32 rows)
    const int wn = w >> 2;        // warp col-block (32 cols)

    // LDG / STS mappings
    const int a_r = t >> 1;                  // A row 0..127
    const int a_c = (t & 1) * 8;             // A col base (floats); 2 float4/thread
    const int y_k = t >> 4;                  // Y row 0..15
    const int y_c = (t & 15) * 4;            // Y col base; 1 float4/thread

    float4 cA[2], cY, nAr[2], nYr;

    auto ldg = [&](int i, float4 (&va)[2], float4& vy) {
        const float* arow = Ab + (size_t)(rowBase + a_r) * N_ + i * BKC + a_c;
        va[0] = *(const float4*)(arow);
        va[1] = *(const float4*)(arow + 4);
        vy = *(const float4*)(Yb + (size_t)(i * BKC + y_k) * O_ + y_c);
    };
    auto sts = [&](int buf, const float4 (&va)[2], const float4& vy) {
        float* pa = sA + buf * SA_BUF + a_r * SA_STRIDE + a_c;
        *(float4*)(pa) = va[0];
        *(float4*)(pa + 4) = va[1];
        *(float4*)(sY + buf * SY_BUF + y_k * SY_STRIDE + y_c) = vy;
    };
    auto stg_outA = [&](int i, const float4 (&va)[2]) {
        if (outAb) {
            float* orow = outAb + (size_t)(rowBase + a_r) * N_ + i * BKC + a_c;
            *(float4*)(orow) = va[0];
            *(float4*)(orow + 4) = va[1];
        }
    };

    float acc[2][4][4];
    #pragma unroll
    for (int mi = 0; mi < 2; mi++)
        #pragma unroll
        for (int ni = 0; ni < 4; ni++)
            #pragma unroll
            for (int j = 0; j < 4; j++) acc[mi][ni][j] = 0.f;

    ldg(0, cA, cY);
    sts(0, cA, cY);
    stg_outA(0, cA);
    __syncthreads();

    for (int i = 0; i < NC; i++) {
        const int buf = i & 1;
        if (i + 1 < NC) ldg(i + 1, nAr, nYr);   // global prefetch in flight

        // ---- compute on buf ----
        const float* a_s = sA + buf * SA_BUF + (wm * 32 + g) * SA_STRIDE + tig;
        const float* y_s = sY + buf * SY_BUF + tig * SY_STRIDE + wn * 32 + g;
        #pragma unroll
        for (int kk = 0; kk < 2; kk++) {
            uint32_t ahi[2][4], alo[2][4];
            #pragma unroll
            for (int mi = 0; mi < 2; mi++) {
                const float* ap = a_s + mi * 16 * SA_STRIDE + kk * 8;
                split_tf32(ap[0],                 ahi[mi][0], alo[mi][0]);
                split_tf32(ap[8 * SA_STRIDE],     ahi[mi][1], alo[mi][1]);
                split_tf32(ap[4],                 ahi[mi][2], alo[mi][2]);
                split_tf32(ap[8 * SA_STRIDE + 4], ahi[mi][3], alo[mi][3]);
            }
            uint32_t bhi[4][2], blo[4][2];
            #pragma unroll
            for (int ni = 0; ni < 4; ni++) {
                const float* yp = y_s + kk * 8 * SY_STRIDE + ni * 8;
                split_tf32(yp[0],             bhi[ni][0], blo[ni][0]);
                split_tf32(yp[4 * SY_STRIDE], bhi[ni][1], blo[ni][1]);
            }
            #pragma unroll
            for (int mi = 0; mi < 2; mi++)
                #pragma unroll
                for (int ni = 0; ni < 4; ni++) {
                    mma8(acc[mi][ni], ahi[mi], bhi[ni]);
                    mma8(acc[mi][ni], alo[mi], bhi[ni]);
                    mma8(acc[mi][ni], ahi[mi], blo[ni]);
                }
        }

        if (i + 1 < NC) {
            sts(buf ^ 1, nAr, nYr);
            stg_outA(i + 1, nAr);
        }
        __syncthreads();
    }

    // ---- epilogue: out = leaky(d[n]*(Z + Y[n,:]) + bias) ----
    #pragma unroll
    for (int mi = 0; mi < 2; mi++) {
        const int r0 = rowBase + wm * 32 + mi * 16 + g;   // rows r0, r0+8
        const float d0 = g_d[(size_t)b * N_ + r0];
        const float d1 = g_d[(size_t)b * N_ + r0 + 8];
        #pragma unroll
        for (int ni = 0; ni < 4; ni++) {
            const int col = wn * 32 + ni * 8 + 2 * tig;
            const float2 bb = *(const float2*)(bias + col);
            const float2 y0 = *(const float2*)(Yb + (size_t)r0 * O_ + col);
            const float2 y1 = *(const float2*)(Yb + (size_t)(r0 + 8) * O_ + col);
            float2 o0, o1;
            o0.x = d0 * (acc[mi][ni][0] + y0.x) + bb.x;
            o0.y = d0 * (acc[mi][ni][1] + y0.y) + bb.y;
            o1.x = d1 * (acc[mi][ni][2] + y1.x) + bb.x;
            o1.y = d1 * (acc[mi][ni][3] + y1.y) + bb.y;
            o0.x = fmaxf(o0.x, ALPHA * o0.x);
            o0.y = fmaxf(o0.y, ALPHA * o0.y);
            o1.x = fmaxf(o1.x, ALPHA * o1.x);
            o1.y = fmaxf(o1.y, ALPHA * o1.y);
            *(float2*)(outX + ((size_t)b * N_ + r0) * O_ + col) = o0;
            *(float2*)(outX + ((size_t)b * N_ + r0 + 8) * O_ + col) = o1;
        }
    }
}

extern "C" void kernel_launch(void* const* d_in, const int* in_sizes, int n_in,
                              void* d_out, int out_size) {
    const float* X    = (const float*)d_in[0];  // [B, N, F]
    const float* A    = (const float*)d_in[1];  // [B, N, N]
    const float* W    = (const float*)d_in[2];  // [F, O]
    const float* bias = (const float*)d_in[3];  // [O]

    const size_t nX = (size_t)B_ * N_ * O_;
    const size_t nA = (size_t)B_ * N_ * N_;
    float* outX = (float*)d_out;
    float* outA = ((size_t)out_size >= nX + nA) ? outX + nX : nullptr;

    prep_kernel<<<B_ * N_ / 8, 256>>>(A, X, W);
    dim3 grid(N_ / BM, B_);
    gemm_tc<<<grid, 256>>>(A, bias, outX, outA);
}

// round 8
// speedup vs baseline: 1.4899x; 1.1220x over previous
#include <cuda_runtime.h>
#include <cstdint>

#define B_ 8
#define N_ 2048
#define F_ 64
#define O_ 64
#define ALPHA 0.2f

#define BM  64
#define BKC 16
#define NC  (N_ / BKC)        // 128 chunks
#define SA_STRIDE 20          // floats; 20%32==4 -> A-frag lanes g*20+tig distinct mod 32
#define SY_STRIDE 72          // floats; 72%32==8 -> B-frag lanes tig*8+g distinct; >= 64 cols
#define SA_BUF (BM * SA_STRIDE)   // 1280 floats per variant per buf
#define SY_BUF (BKC * SY_STRIDE)  // 1152 floats per variant per buf
// static smem: 4 arrays: 2*1280*2 + 2*1152*2 = 9728 floats = 38912 B < 48 KB
// -> 2 CTAs/SM (77.8 KB combined) for occ 25%

// Scratch (allocation-free rule: __device__ globals)
__device__ float g_d[B_ * N_];               // d[b,n] = rsqrt(rowsum+1)
__device__ float g_Y[(size_t)B_ * N_ * O_];  // Y[b,k,o] = d[b,k]*(X@W)[b,k,o]

// ---------------------------------------------------------------------------
// Pass 1: per A-row rowsum -> d, fused with Y = d*(X@W).
// ---------------------------------------------------------------------------
__global__ void __launch_bounds__(256) prep_kernel(const float* __restrict__ A,
                                                   const float* __restrict__ X,
                                                   const float* __restrict__ W) {
    __shared__ float sW[F_ * O_];
    __shared__ float sX[8][F_];
    const int t = threadIdx.x;
    const int warp = t >> 5;
    const int lane = t & 31;
    const int row = blockIdx.x * 8 + warp;   // flattened [b][n]

    #pragma unroll
    for (int i = t; i < F_ * O_; i += 256) sW[i] = W[i];
    #pragma unroll
    for (int i = t; i < 8 * F_; i += 256)
        sX[i >> 6][i & 63] = X[(size_t)blockIdx.x * 8 * F_ + i];
    __syncthreads();

    const float4* arow = (const float4*)(A + (size_t)row * N_);
    float s = 0.f;
    #pragma unroll 4
    for (int i = lane; i < N_ / 4; i += 32) {
        float4 v = arow[i];
        s += (v.x + v.y) + (v.z + v.w);
    }
    #pragma unroll
    for (int off = 16; off; off >>= 1) s += __shfl_xor_sync(0xffffffffu, s, off);
    const float dd = rsqrtf(s + 1.0f);
    if (lane == 0) g_d[row] = dd;

    float acc0 = 0.f, acc1 = 0.f;
    #pragma unroll
    for (int f = 0; f < F_; f++) {
        const float xv = sX[warp][f];
        acc0 += xv * sW[f * O_ + lane];
        acc1 += xv * sW[f * O_ + lane + 32];
    }
    g_Y[(size_t)row * O_ + lane]      = dd * acc0;
    g_Y[(size_t)row * O_ + lane + 32] = dd * acc1;
}

// ---------------------------------------------------------------------------
// TF32 helpers (sm_80+ PTX; compiles for plain sm_100)
// ---------------------------------------------------------------------------
__device__ __forceinline__ void split_tf32(float x, float& hi, float& lo) {
    uint32_t h;
    asm("cvt.rna.tf32.f32 %0, %1;" : "=r"(h) : "f"(x));
    hi = __uint_as_float(h);
    lo = x - hi;
}
__device__ __forceinline__ void mma8(float* c, const float* a, const float* b) {
    asm("mma.sync.aligned.m16n8k8.row.col.f32.tf32.tf32.f32 "
        "{%0,%1,%2,%3}, {%4,%5,%6,%7}, {%8,%9}, {%0,%1,%2,%3};"
        : "+f"(c[0]), "+f"(c[1]), "+f"(c[2]), "+f"(c[3])
        : "r"(__float_as_uint(a[0])), "r"(__float_as_uint(a[1])),
          "r"(__float_as_uint(a[2])), "r"(__float_as_uint(a[3])),
          "r"(__float_as_uint(b[0])), "r"(__float_as_uint(b[1])));
}

// ---------------------------------------------------------------------------
// Pass 2: Z = A @ Y via mma.sync tf32 (3xTF32), tiles pre-split hi/lo in SMEM
// (each element split exactly once at STS time). Fused A copy-out + epilogue
// out = leaky(d[n]*(Z + Y[n,:]) + bias).
// 256 CTAs (32 row-tiles x 8 batches), 256 threads (8 warps: 4 M-groups x
// 2 N-groups, warp tile 16x32), double-buffered, 2 CTAs/SM.
// ---------------------------------------------------------------------------
__global__ void __launch_bounds__(256, 2) gemm_tc(const float* __restrict__ A,
                                                  const float* __restrict__ bias,
                                                  float* __restrict__ outX,
                                                  float* __restrict__ outA) {
    __shared__ float sAh[2 * SA_BUF];
    __shared__ float sAl[2 * SA_BUF];
    __shared__ float sYh[2 * SY_BUF];
    __shared__ float sYl[2 * SY_BUF];

    const int b = blockIdx.y;
    const int rowBase = blockIdx.x * BM;
    const float* Ab = A + (size_t)b * N_ * N_;
    float* outAb = outA ? outA + (size_t)b * N_ * N_ : nullptr;
    const float* Yb = g_Y + (size_t)b * N_ * O_;

    const int t = threadIdx.x;
    const int w = t >> 5;
    const int lane = t & 31;
    const int g = lane >> 2;      // fragment group (0..7)
    const int tig = lane & 3;     // thread-in-group
    const int wm = w & 3;         // warp row-block (16 rows)
    const int wn = w >> 2;        // warp col-block (32 cols)

    // Loader mappings: 1 float4 of A + 1 float4 of Y per thread per chunk
    const int a_r = t >> 2;                  // A row 0..63
    const int a_c = (t & 3) * 4;             // A col base (floats)
    const int y_k = t >> 4;                  // Y row 0..15
    const int y_c = (t & 15) * 4;            // Y col base

    float4 cA, cY, nA, nY;

    auto ldg = [&](int i, float4& va, float4& vy) {
        va = *(const float4*)(Ab + (size_t)(rowBase + a_r) * N_ + i * BKC + a_c);
        vy = *(const float4*)(Yb + (size_t)(i * BKC + y_k) * O_ + y_c);
    };
    auto sts = [&](int buf, const float4& va, const float4& vy) {
        float4 h, l;
        split_tf32(va.x, h.x, l.x); split_tf32(va.y, h.y, l.y);
        split_tf32(va.z, h.z, l.z); split_tf32(va.w, h.w, l.w);
        const int ao = buf * SA_BUF + a_r * SA_STRIDE + a_c;
        *(float4*)(sAh + ao) = h;
        *(float4*)(sAl + ao) = l;
        split_tf32(vy.x, h.x, l.x); split_tf32(vy.y, h.y, l.y);
        split_tf32(vy.z, h.z, l.z); split_tf32(vy.w, h.w, l.w);
        const int yo = buf * SY_BUF + y_k * SY_STRIDE + y_c;
        *(float4*)(sYh + yo) = h;
        *(float4*)(sYl + yo) = l;
    };
    auto stg_outA = [&](int i, const float4& va) {
        if (outAb)
            *(float4*)(outAb + (size_t)(rowBase + a_r) * N_ + i * BKC + a_c) = va;
    };

    float acc[4][4];
    #pragma unroll
    for (int ni = 0; ni < 4; ni++)
        #pragma unroll
        for (int j = 0; j < 4; j++) acc[ni][j] = 0.f;

    ldg(0, cA, cY);
    sts(0, cA, cY);
    stg_outA(0, cA);
    __syncthreads();

    const int a_base = (wm * 16 + g) * SA_STRIDE + tig;
    const int y_base = tig * SY_STRIDE + wn * 32 + g;

    for (int i = 0; i < NC; i++) {
        const int buf = i & 1;
        if (i + 1 < NC) ldg(i + 1, nA, nY);   // global prefetch in flight

        // ---- compute on buf: pure LDS + MMA ----
        const float* ah = sAh + buf * SA_BUF + a_base;
        const float* al = sAl + buf * SA_BUF + a_base;
        const float* yh = sYh + buf * SY_BUF + y_base;
        const float* yl = sYl + buf * SY_BUF + y_base;
        #pragma unroll
        for (int kk = 0; kk < 2; kk++) {
            float fah[4], fal[4];
            fah[0] = ah[kk * 8];                     fal[0] = al[kk * 8];
            fah[1] = ah[8 * SA_STRIDE + kk * 8];     fal[1] = al[8 * SA_STRIDE + kk * 8];
            fah[2] = ah[kk * 8 + 4];                 fal[2] = al[kk * 8 + 4];
            fah[3] = ah[8 * SA_STRIDE + kk * 8 + 4]; fal[3] = al[8 * SA_STRIDE + kk * 8 + 4];
            #pragma unroll
            for (int ni = 0; ni < 4; ni++) {
                const int yo = kk * 8 * SY_STRIDE + ni * 8;
                float fbh[2], fbl[2];
                fbh[0] = yh[yo];                  fbl[0] = yl[yo];
                fbh[1] = yh[yo + 4 * SY_STRIDE];  fbl[1] = yl[yo + 4 * SY_STRIDE];
                mma8(acc[ni], fah, fbh);
                mma8(acc[ni], fal, fbh);
                mma8(acc[ni], fah, fbl);
            }
        }

        if (i + 1 < NC) {
            sts(buf ^ 1, nA, nY);
            stg_outA(i + 1, nA);
        }
        __syncthreads();
    }

    // ---- epilogue: out = leaky(d[n]*(Z + Y[n,:]) + bias) ----
    const int r0 = rowBase + wm * 16 + g;   // rows r0 (c[0,1]) and r0+8 (c[2,3])
    const float d0 = g_d[(size_t)b * N_ + r0];
    const float d1 = g_d[(size_t)b * N_ + r0 + 8];
    #pragma unroll
    for (int ni = 0; ni < 4; ni++) {
        const int col = wn * 32 + ni * 8 + 2 * tig;
        const float2 bb = *(const float2*)(bias + col);
        const float2 y0 = *(const float2*)(Yb + (size_t)r0 * O_ + col);
        const float2 y1 = *(const float2*)(Yb + (size_t)(r0 + 8) * O_ + col);
        float2 o0, o1;
        o0.x = d0 * (acc[ni][0] + y0.x) + bb.x;
        o0.y = d0 * (acc[ni][1] + y0.y) + bb.y;
        o1.x = d1 * (acc[ni][2] + y1.x) + bb.x;
        o1.y = d1 * (acc[ni][3] + y1.y) + bb.y;
        o0.x = fmaxf(o0.x, ALPHA * o0.x);
        o0.y = fmaxf(o0.y, ALPHA * o0.y);
        o1.x = fmaxf(o1.x, ALPHA * o1.x);
        o1.y = fmaxf(o1.y, ALPHA * o1.y);
        *(float2*)(outX + ((size_t)b * N_ + r0) * O_ + col) = o0;
        *(float2*)(outX + ((size_t)b * N_ + r0 + 8) * O_ + col) = o1;
    }
}

extern "C" void kernel_launch(void* const* d_in, const int* in_sizes, int n_in,
                              void* d_out, int out_size) {
    const float* X    = (const float*)d_in[0];  // [B, N, F]
    const float* A    = (const float*)d_in[1];  // [B, N, N]
    const float* W    = (const float*)d_in[2];  // [F, O]
    const float* bias = (const float*)d_in[3];  // [O]

    const size_t nX = (size_t)B_ * N_ * O_;
    const size_t nA = (size_t)B_ * N_ * N_;
    float* outX = (float*)d_out;
    float* outA = ((size_t)out_size >= nX + nA) ? outX + nX : nullptr;

    prep_kernel<<<B_ * N_ / 8, 256>>>(A, X, W);
    dim3 grid(N_ / BM, B_);
    gemm_tc<<<grid, 256>>>(A, bias, outX, outA);
}

// round 9
// speedup vs baseline: 1.5604x; 1.0473x over previous
#include <cuda_runtime.h>
#include <cstdint>

#define B_ 8
#define N_ 2048
#define F_ 64
#define O_ 64
#define ALPHA 0.2f

#define BM  64
#define BKC 16
#define KSPLIT 2
#define KHALF (N_ / KSPLIT)       // 1024
#define NCH (KHALF / BKC)         // 64 chunks per CTA
#define SA_STRIDE 24              // perm layout: 16 slots + pad; fl2 banks 12g+t distinct
#define SY_STRIDE 72              // row-major Y; scalar b-frag loads conflict-free
#define SA_BUF (BM * SA_STRIDE)   // 1536 floats per variant per buf
#define SY_BUF (BKC * SY_STRIDE)  // 1152 floats per buf
// static smem: (2*1536)*2 + 2*1152 = 8448 floats = 33792 B < 48 KB

// Scratch (allocation-free rule: __device__ globals)
__device__ float g_d[B_ * N_];                    // d[b,n] = rsqrt(rowsum+1)
__device__ float g_Y[(size_t)B_ * N_ * O_];       // Y = d*(X@W)
__device__ float g_Zp[(size_t)KSPLIT * B_ * N_ * O_];  // 8 MB K-split partials

// ---------------------------------------------------------------------------
// Pass 1: per A-row rowsum -> d, fused with Y = d*(X@W).
// ---------------------------------------------------------------------------
__global__ void __launch_bounds__(256) prep_kernel(const float* __restrict__ A,
                                                   const float* __restrict__ X,
                                                   const float* __restrict__ W) {
    __shared__ float sW[F_ * O_];
    __shared__ float sX[8][F_];
    const int t = threadIdx.x;
    const int warp = t >> 5;
    const int lane = t & 31;
    const int row = blockIdx.x * 8 + warp;   // flattened [b][n]

    #pragma unroll
    for (int i = t; i < F_ * O_; i += 256) sW[i] = W[i];
    #pragma unroll
    for (int i = t; i < 8 * F_; i += 256)
        sX[i >> 6][i & 63] = X[(size_t)blockIdx.x * 8 * F_ + i];
    __syncthreads();

    const float4* arow = (const float4*)(A + (size_t)row * N_);
    float s = 0.f;
    #pragma unroll 4
    for (int i = lane; i < N_ / 4; i += 32) {
        float4 v = arow[i];
        s += (v.x + v.y) + (v.z + v.w);
    }
    #pragma unroll
    for (int off = 16; off; off >>= 1) s += __shfl_xor_sync(0xffffffffu, s, off);
    const float dd = rsqrtf(s + 1.0f);
    if (lane == 0) g_d[row] = dd;

    float acc0 = 0.f, acc1 = 0.f;
    #pragma unroll
    for (int f = 0; f < F_; f++) {
        const float xv = sX[warp][f];
        acc0 += xv * sW[f * O_ + lane];
        acc1 += xv * sW[f * O_ + lane + 32];
    }
    g_Y[(size_t)row * O_ + lane]      = dd * acc0;
    g_Y[(size_t)row * O_ + lane + 32] = dd * acc1;
}

// ---------------------------------------------------------------------------
// TF32 helpers (sm_80+ PTX; compiles for plain sm_100)
// ---------------------------------------------------------------------------
__device__ __forceinline__ void split_tf32(float x, float& hi, float& lo) {
    uint32_t h;
    asm("cvt.rna.tf32.f32 %0, %1;" : "=r"(h) : "f"(x));
    hi = __uint_as_float(h);
    lo = x - hi;
}
__device__ __forceinline__ float round_tf32(float x) {
    uint32_t h;
    asm("cvt.rna.tf32.f32 %0, %1;" : "=r"(h) : "f"(x));
    return __uint_as_float(h);
}
__device__ __forceinline__ void mma8(float* c, const float* a, const float* b) {
    asm("mma.sync.aligned.m16n8k8.row.col.f32.tf32.tf32.f32 "
        "{%0,%1,%2,%3}, {%4,%5,%6,%7}, {%8,%9}, {%0,%1,%2,%3};"
        : "+f"(c[0]), "+f"(c[1]), "+f"(c[2]), "+f"(c[3])
        : "r"(__float_as_uint(a[0])), "r"(__float_as_uint(a[1])),
          "r"(__float_as_uint(a[2])), "r"(__float_as_uint(a[3])),
          "r"(__float_as_uint(b[0])), "r"(__float_as_uint(b[1])));
}

// ---------------------------------------------------------------------------
// Pass 2: Z-partial = A[:, kHalf] @ Y[kHalf, :] via mma.sync tf32, 2-product
// split (A exact as hi+lo, Y rounded to tf32). Fused A copy-out.
// grid (32 row-tiles, 8 batches, 2 k-halves) = 512 CTAs, 256 thr, occ ~42%.
// A stored in fragment-major perm layout -> LDS.64 fragment loads.
// ---------------------------------------------------------------------------
__global__ void __launch_bounds__(256, 4) gemm_tc(const float* __restrict__ A,
                                                  float* __restrict__ outA) {
    __shared__ float sAh[2 * SA_BUF];
    __shared__ float sAl[2 * SA_BUF];
    __shared__ float sYh[2 * SY_BUF];

    const int b = blockIdx.y;
    const int ks = blockIdx.z;
    const int rowBase = blockIdx.x * BM;
    const int kBase = ks * KHALF;
    const float* Ab = A + (size_t)b * N_ * N_;
    float* outAb = outA ? outA + (size_t)b * N_ * N_ : nullptr;
    const float* Yb = g_Y + (size_t)b * N_ * O_;

    const int t = threadIdx.x;
    const int w = t >> 5;
    const int lane = t & 31;
    const int g = lane >> 2;      // fragment group (0..7)
    const int tig = lane & 3;     // thread-in-group
    const int wm = w & 3;         // warp row-block (16 rows)
    const int wn = w >> 2;        // warp col-block (32 cols)

    // Loader mappings: 1 float4 of A + 1 float4 of Y per thread per chunk
    const int a_r = t >> 2;                  // A row 0..63
    const int a_c = (t & 3) * 4;             // A col base (multiple of 4)
    const int y_k = t >> 4;                  // Y row 0..15
    const int y_c = (t & 15) * 4;            // Y col base
    // perm(c) = (c>>3)*8 + (c&3)*2 + ((c>>2)&1); for c = a_c+j (j=0..3):
    // = P0 + 2j with P0 constant per thread:
    const int a_p0 = ((a_c >> 3) << 3) + ((a_c >> 2) & 1);

    float4 cA, cY, nA, nY;

    auto ldg = [&](int i, float4& va, float4& vy) {
        va = *(const float4*)(Ab + (size_t)(rowBase + a_r) * N_ + kBase + i * BKC + a_c);
        vy = *(const float4*)(Yb + (size_t)(kBase + i * BKC + y_k) * O_ + y_c);
    };
    auto sts = [&](int buf, const float4& va, const float4& vy) {
        float h, l;
        float* ph = sAh + buf * SA_BUF + a_r * SA_STRIDE + a_p0;
        float* pl = sAl + buf * SA_BUF + a_r * SA_STRIDE + a_p0;
        split_tf32(va.x, h, l); ph[0] = h; pl[0] = l;
        split_tf32(va.y, h, l); ph[2] = h; pl[2] = l;
        split_tf32(va.z, h, l); ph[4] = h; pl[4] = l;
        split_tf32(va.w, h, l); ph[6] = h; pl[6] = l;
        float4 yh;
        yh.x = round_tf32(vy.x); yh.y = round_tf32(vy.y);
        yh.z = round_tf32(vy.z); yh.w = round_tf32(vy.w);
        *(float4*)(sYh + buf * SY_BUF + y_k * SY_STRIDE + y_c) = yh;
    };
    auto stg_outA = [&](int i, const float4& va) {
        if (outAb)
            *(float4*)(outAb + (size_t)(rowBase + a_r) * N_ + kBase + i * BKC + a_c) = va;
    };

    float acc[4][4];
    #pragma unroll
    for (int ni = 0; ni < 4; ni++)
        #pragma unroll
        for (int j = 0; j < 4; j++) acc[ni][j] = 0.f;

    ldg(0, cA, cY);
    sts(0, cA, cY);
    stg_outA(0, cA);
    __syncthreads();

    const int a_base = (wm * 16 + g) * SA_STRIDE + 2 * tig;
    const int y_base = tig * SY_STRIDE + wn * 32 + g;

    for (int i = 0; i < NCH; i++) {
        const int buf = i & 1;
        if (i + 1 < NCH) ldg(i + 1, nA, nY);   // global prefetch in flight

        // ---- compute on buf: vectorized A-frag LDS.64 + scalar Y + MMA ----
        const float* ah = sAh + buf * SA_BUF + a_base;
        const float* al = sAl + buf * SA_BUF + a_base;
        const float* yh = sYh + buf * SY_BUF + y_base;
        #pragma unroll
        for (int kk = 0; kk < 2; kk++) {
            const float2 h0 = *(const float2*)(ah + kk * 8);
            const float2 h1 = *(const float2*)(ah + 8 * SA_STRIDE + kk * 8);
            const float2 l0 = *(const float2*)(al + kk * 8);
            const float2 l1 = *(const float2*)(al + 8 * SA_STRIDE + kk * 8);
            const float fah[4] = {h0.x, h1.x, h0.y, h1.y};
            const float fal[4] = {l0.x, l1.x, l0.y, l1.y};
            #pragma unroll
            for (int ni = 0; ni < 4; ni++) {
                const int yo = kk * 8 * SY_STRIDE + ni * 8;
                const float fb[2] = {yh[yo], yh[yo + 4 * SY_STRIDE]};
                mma8(acc[ni], fah, fb);
                mma8(acc[ni], fal, fb);
            }
        }

        if (i + 1 < NCH) {
            sts(buf ^ 1, nA, nY);
            stg_outA(i + 1, nA);
        }
        __syncthreads();
    }

    // ---- store raw partial Z to scratch ----
    float* zp = g_Zp + ((size_t)(ks * B_ + b) * N_) * O_;
    const int r0 = rowBase + wm * 16 + g;
    #pragma unroll
    for (int ni = 0; ni < 4; ni++) {
        const int col = wn * 32 + ni * 8 + 2 * tig;
        *(float2*)(zp + (size_t)r0 * O_ + col)       = make_float2(acc[ni][0], acc[ni][1]);
        *(float2*)(zp + (size_t)(r0 + 8) * O_ + col) = make_float2(acc[ni][2], acc[ni][3]);
    }
}

// ---------------------------------------------------------------------------
// Pass 3: combine partials + diagonal + scale + bias + leaky. ~16 MB traffic.
// ---------------------------------------------------------------------------
__global__ void __launch_bounds__(256) combine_kernel(const float* __restrict__ bias,
                                                      float* __restrict__ outX) {
    const int t = threadIdx.x;
    const int r = blockIdx.x * 16 + (t >> 4);     // global row 0..16383
    const int c = (t & 15) * 4;
    const size_t off = (size_t)r * O_ + c;
    const float4 z0 = *(const float4*)(g_Zp + off);
    const float4 z1 = *(const float4*)(g_Zp + (size_t)B_ * N_ * O_ + off);
    const float4 yv = *(const float4*)(g_Y + off);
    const float4 bb = *(const float4*)(bias + c);
    const float dd = g_d[r];
    float4 o;
    o.x = dd * (z0.x + z1.x + yv.x) + bb.x;
    o.y = dd * (z0.y + z1.y + yv.y) + bb.y;
    o.z = dd * (z0.z + z1.z + yv.z) + bb.z;
    o.w = dd * (z0.w + z1.w + yv.w) + bb.w;
    o.x = fmaxf(o.x, ALPHA * o.x);
    o.y = fmaxf(o.y, ALPHA * o.y);
    o.z = fmaxf(o.z, ALPHA * o.z);
    o.w = fmaxf(o.w, ALPHA * o.w);
    *(float4*)(outX + off) = o;
}

extern "C" void kernel_launch(void* const* d_in, const int* in_sizes, int n_in,
                              void* d_out, int out_size) {
    const float* X    = (const float*)d_in[0];  // [B, N, F]
    const float* A    = (const float*)d_in[1];  // [B, N, N]
    const float* W    = (const float*)d_in[2];  // [F, O]
    const float* bias = (const float*)d_in[3];  // [O]

    const size_t nX = (size_t)B_ * N_ * O_;
    const size_t nA = (size_t)B_ * N_ * N_;
    float* outX = (float*)d_out;
    float* outA = ((size_t)out_size >= nX + nA) ? outX + nX : nullptr;

    prep_kernel<<<B_ * N_ / 8, 256>>>(A, X, W);
    dim3 grid(N_ / BM, B_, KSPLIT);
    gemm_tc<<<grid, 256>>>(A, outA);
    combine_kernel<<<B_ * N_ / 16, 256>>>(bias, outX);
}

// round 10
// speedup vs baseline: 2.0436x; 1.3097x over previous
#include <cuda_runtime.h>
#include <cstdint>

#define B_ 8
#define N_ 2048
#define F_ 64
#define O_ 64
#define ALPHA 0.2f

#define BM  64
#define BKC 16
#define KSPLIT 4
#define KPART (N_ / KSPLIT)       // 512
#define NCH (KPART / BKC)         // 32 chunks per CTA
#define SA_STRIDE 24              // perm layout: 16 slots + pad
#define SY_STRIDE 72              // row-major Y; scalar b-frag loads conflict-free
#define SA_BUF (BM * SA_STRIDE)   // 1536 floats per buf
#define SY_BUF (BKC * SY_STRIDE)  // 1152 floats per buf
// static smem: 2*1536 + 2*1152 = 5376 floats = 21504 B -> 4 CTAs/SM OK

// Scratch (allocation-free rule: __device__ globals)
__device__ float g_d[B_ * N_];                         // d[b,n] = rsqrt(rowsum+1)
__device__ float g_Y[(size_t)B_ * N_ * O_];            // Y = d*(X@W)
__device__ float g_Zp[(size_t)KSPLIT * B_ * N_ * O_];  // 16 MB K-split partials

// ---------------------------------------------------------------------------
// Pass 1: per A-row rowsum -> d, fused with Y = d*(X@W).
// ---------------------------------------------------------------------------
__global__ void __launch_bounds__(256) prep_kernel(const float* __restrict__ A,
                                                   const float* __restrict__ X,
                                                   const float* __restrict__ W) {
    __shared__ float sW[F_ * O_];
    __shared__ float sX[8][F_];
    const int t = threadIdx.x;
    const int warp = t >> 5;
    const int lane = t & 31;
    const int row = blockIdx.x * 8 + warp;   // flattened [b][n]

    #pragma unroll
    for (int i = t; i < F_ * O_; i += 256) sW[i] = W[i];
    #pragma unroll
    for (int i = t; i < 8 * F_; i += 256)
        sX[i >> 6][i & 63] = X[(size_t)blockIdx.x * 8 * F_ + i];
    __syncthreads();

    const float4* arow = (const float4*)(A + (size_t)row * N_);
    float s = 0.f;
    #pragma unroll 4
    for (int i = lane; i < N_ / 4; i += 32) {
        float4 v = arow[i];
        s += (v.x + v.y) + (v.z + v.w);
    }
    #pragma unroll
    for (int off = 16; off; off >>= 1) s += __shfl_xor_sync(0xffffffffu, s, off);
    const float dd = rsqrtf(s + 1.0f);
    if (lane == 0) g_d[row] = dd;

    float acc0 = 0.f, acc1 = 0.f;
    #pragma unroll
    for (int f = 0; f < F_; f++) {
        const float xv = sX[warp][f];
        acc0 += xv * sW[f * O_ + lane];
        acc1 += xv * sW[f * O_ + lane + 32];
    }
    g_Y[(size_t)row * O_ + lane]      = dd * acc0;
    g_Y[(size_t)row * O_ + lane + 32] = dd * acc1;
}

// ---------------------------------------------------------------------------
// TF32 helpers (sm_80+ PTX; compiles for plain sm_100)
// ---------------------------------------------------------------------------
__device__ __forceinline__ float round_tf32(float x) {
    uint32_t h;
    asm("cvt.rna.tf32.f32 %0, %1;" : "=r"(h) : "f"(x));
    return __uint_as_float(h);
}
__device__ __forceinline__ void mma8(float* c, const float* a, const float* b) {
    asm("mma.sync.aligned.m16n8k8.row.col.f32.tf32.tf32.f32 "
        "{%0,%1,%2,%3}, {%4,%5,%6,%7}, {%8,%9}, {%0,%1,%2,%3};"
        : "+f"(c[0]), "+f"(c[1]), "+f"(c[2]), "+f"(c[3])
        : "r"(__float_as_uint(a[0])), "r"(__float_as_uint(a[1])),
          "r"(__float_as_uint(a[2])), "r"(__float_as_uint(a[3])),
          "r"(__float_as_uint(b[0])), "r"(__float_as_uint(b[1])));
}

// ---------------------------------------------------------------------------
// Pass 2: Z-partial = A[:, kpart] @ Y[kpart, :] via mma.sync tf32 single
// product (A and Y rounded to tf32 at STS). Fused A copy-out.
// grid (32 row-tiles, 8 batches, 4 k-parts) = 1024 CTAs, 256 thr,
// 4 CTAs/SM -> occ ~50%. A in fragment-major perm layout (LDS.64 frags).
// ---------------------------------------------------------------------------
__global__ void __launch_bounds__(256, 4) gemm_tc(const float* __restrict__ A,
                                                  float* __restrict__ outA) {
    __shared__ float sAh[2 * SA_BUF];
    __shared__ float sYh[2 * SY_BUF];

    const int b = blockIdx.y;
    const int ks = blockIdx.z;
    const int rowBase = blockIdx.x * BM;
    const int kBase = ks * KPART;
    const float* Ab = A + (size_t)b * N_ * N_;
    float* outAb = outA ? outA + (size_t)b * N_ * N_ : nullptr;
    const float* Yb = g_Y + (size_t)b * N_ * O_;

    const int t = threadIdx.x;
    const int w = t >> 5;
    const int lane = t & 31;
    const int g = lane >> 2;      // fragment group (0..7)
    const int tig = lane & 3;     // thread-in-group
    const int wm = w & 3;         // warp row-block (16 rows)
    const int wn = w >> 2;        // warp col-block (32 cols)

    // Loader mappings: 1 float4 of A + 1 float4 of Y per thread per chunk
    const int a_r = t >> 2;                  // A row 0..63
    const int a_c = (t & 3) * 4;             // A col base (multiple of 4)
    const int y_k = t >> 4;                  // Y row 0..15
    const int y_c = (t & 15) * 4;            // Y col base
    // perm(c) = (c>>3)*8 + (c&3)*2 + ((c>>2)&1); for c = a_c + j:
    const int a_p0 = ((a_c >> 3) << 3) + ((a_c >> 2) & 1);

    float4 cA, cY, nA, nY;

    auto ldg = [&](int i, float4& va, float4& vy) {
        va = *(const float4*)(Ab + (size_t)(rowBase + a_r) * N_ + kBase + i * BKC + a_c);
        vy = *(const float4*)(Yb + (size_t)(kBase + i * BKC + y_k) * O_ + y_c);
    };
    auto sts = [&](int buf, const float4& va, const float4& vy) {
        float* ph = sAh + buf * SA_BUF + a_r * SA_STRIDE + a_p0;
        ph[0] = round_tf32(va.x);
        ph[2] = round_tf32(va.y);
        ph[4] = round_tf32(va.z);
        ph[6] = round_tf32(va.w);
        float4 yh;
        yh.x = round_tf32(vy.x); yh.y = round_tf32(vy.y);
        yh.z = round_tf32(vy.z); yh.w = round_tf32(vy.w);
        *(float4*)(sYh + buf * SY_BUF + y_k * SY_STRIDE + y_c) = yh;
    };
    auto stg_outA = [&](int i, const float4& va) {
        if (outAb)
            *(float4*)(outAb + (size_t)(rowBase + a_r) * N_ + kBase + i * BKC + a_c) = va;
    };

    float acc[4][4];
    #pragma unroll
    for (int ni = 0; ni < 4; ni++)
        #pragma unroll
        for (int j = 0; j < 4; j++) acc[ni][j] = 0.f;

    ldg(0, cA, cY);
    sts(0, cA, cY);
    stg_outA(0, cA);
    __syncthreads();

    const int a_base = (wm * 16 + g) * SA_STRIDE + 2 * tig;
    const int y_base = tig * SY_STRIDE + wn * 32 + g;

    for (int i = 0; i < NCH; i++) {
        const int buf = i & 1;
        if (i + 1 < NCH) ldg(i + 1, nA, nY);   // global prefetch in flight

        // ---- compute on buf: LDS.64 A-frags + scalar Y + MMA ----
        const float* ah = sAh + buf * SA_BUF + a_base;
        const float* yh = sYh + buf * SY_BUF + y_base;
        #pragma unroll
        for (int kk = 0; kk < 2; kk++) {
            const float2 h0 = *(const float2*)(ah + kk * 8);
            const float2 h1 = *(const float2*)(ah + 8 * SA_STRIDE + kk * 8);
            const float fah[4] = {h0.x, h1.x, h0.y, h1.y};
            #pragma unroll
            for (int ni = 0; ni < 4; ni++) {
                const int yo = kk * 8 * SY_STRIDE + ni * 8;
                const float fb[2] = {yh[yo], yh[yo + 4 * SY_STRIDE]};
                mma8(acc[ni], fah, fb);
            }
        }

        if (i + 1 < NCH) {
            sts(buf ^ 1, nA, nY);
            stg_outA(i + 1, nA);
        }
        __syncthreads();
    }

    // ---- store raw partial Z to scratch ----
    float* zp = g_Zp + ((size_t)(ks * B_ + b) * N_) * O_;
    const int r0 = rowBase + wm * 16 + g;
    #pragma unroll
    for (int ni = 0; ni < 4; ni++) {
        const int col = wn * 32 + ni * 8 + 2 * tig;
        *(float2*)(zp + (size_t)r0 * O_ + col)       = make_float2(acc[ni][0], acc[ni][1]);
        *(float2*)(zp + (size_t)(r0 + 8) * O_ + col) = make_float2(acc[ni][2], acc[ni][3]);
    }
}

// ---------------------------------------------------------------------------
// Pass 3: combine 4 partials + diagonal + scale + bias + leaky. ~28 MB traffic.
// ---------------------------------------------------------------------------
__global__ void __launch_bounds__(256) combine_kernel(const float* __restrict__ bias,
                                                      float* __restrict__ outX) {
    const int t = threadIdx.x;
    const int r = blockIdx.x * 16 + (t >> 4);     // global row 0..16383
    const int c = (t & 15) * 4;
    const size_t off = (size_t)r * O_ + c;
    const size_t part = (size_t)B_ * N_ * O_;
    const float4 z0 = *(const float4*)(g_Zp + off);
    const float4 z1 = *(const float4*)(g_Zp + part + off);
    const float4 z2 = *(const float4*)(g_Zp + 2 * part + off);
    const float4 z3 = *(const float4*)(g_Zp + 3 * part + off);
    const float4 yv = *(const float4*)(g_Y + off);
    const float4 bb = *(const float4*)(bias + c);
    const float dd = g_d[r];
    float4 o;
    o.x = dd * (((z0.x + z1.x) + (z2.x + z3.x)) + yv.x) + bb.x;
    o.y = dd * (((z0.y + z1.y) + (z2.y + z3.y)) + yv.y) + bb.y;
    o.z = dd * (((z0.z + z1.z) + (z2.z + z3.z)) + yv.z) + bb.z;
    o.w = dd * (((z0.w + z1.w) + (z2.w + z3.w)) + yv.w) + bb.w;
    o.x = fmaxf(o.x, ALPHA * o.x);
    o.y = fmaxf(o.y, ALPHA * o.y);
    o.z = fmaxf(o.z, ALPHA * o.z);
    o.w = fmaxf(o.w, ALPHA * o.w);
    *(float4*)(outX + off) = o;
}

extern "C" void kernel_launch(void* const* d_in, const int* in_sizes, int n_in,
                              void* d_out, int out_size) {
    const float* X    = (const float*)d_in[0];  // [B, N, F]
    const float* A    = (const float*)d_in[1];  // [B, N, N]
    const float* W    = (const float*)d_in[2];  // [F, O]
    const float* bias = (const float*)d_in[3];  // [O]

    const size_t nX = (size_t)B_ * N_ * O_;
    const size_t nA = (size_t)B_ * N_ * N_;
    float* outX = (float*)d_out;
    float* outA = ((size_t)out_size >= nX + nA) ? outX + nX : nullptr;

    prep_kernel<<<B_ * N_ / 8, 256>>>(A, X, W);
    dim3 grid(N_ / BM, B_, KSPLIT);
    gemm_tc<<<grid, 256>>>(A, outA);
    combine_kernel<<<B_ * N_ / 16, 256>>>(bias, outX);
}